// round 5
// baseline (speedup 1.0000x reference)
#include <cuda_runtime.h>
#include <cuda_bf16.h>

#define BSZ       64
#define SEQLEN    512
#define NT        48
#define NT2       (NT * NT)
#define START_TAG 46
#define END_TAG   47
#define TPB       384   // 48 columns x 8 lanes

// Runtime-detected target dtype flag (1 = int64, 0 = int32).
__device__ int g_is64;

// Prep kernel: zero the output scalar and detect target dtype.
// If target is int64 (values 0..45), every odd int32 word is 0.
// For int32 data the odd words are random tags in [0,46) -> all-zero
// probability ~ (1/46)^32 ~ 0.
__global__ void crf_prep(const int* __restrict__ tgt32, float* __restrict__ out) {
    int lane = threadIdx.x;
    int v = tgt32[2 * lane + 1];
    int all0 = __all_sync(0xffffffffu, v == 0);
    if (lane == 0) {
        g_is64 = all0;
        out[0] = 0.0f;
    }
}

// One CTA per batch. 48 columns (j), 8 lanes per column reducing over i.
// Per step t:
//   raw[j] = log( sum_i exp( r[i] - m + tr[t][i][j] ) ),  m = r[0]
//   r <- raw,  C += m          (true forward value = r + C)
// The per-column max of the reference is replaced by the scalar offset m,
// which keeps exp arguments bounded (values are logsumexps of the same
// distribution; spread is a few units). EPS=1e-12 is negligible since the
// sum always contains a term >= exp(-spread).
__global__ __launch_bounds__(TPB, 1) void crf_main(
    const float* __restrict__ tr,
    const void*  __restrict__ tgt,
    float*       __restrict__ out)
{
    __shared__ float shr[2][NT];
    __shared__ float ts_sh;

    const int tid = threadIdx.x;
    const int b   = blockIdx.x;
    const int j   = tid >> 3;   // column 0..47
    const int sub = tid & 7;    // reduction lane 0..7

    const float* __restrict__ tb = tr + (size_t)b * SEQLEN * NT2;

    if (tid == 0) ts_sh = 0.0f;
    // r_1 = transition[b, 0, START, :]
    if (tid < NT) shr[0][tid] = tb[START_TAG * NT + tid];

    // ---- target path score (gathered) ----
    const int is64 = g_is64;
    float ts = 0.0f;
    for (int s = tid; s < SEQLEN; s += TPB) {
        int cur, prv;
        if (is64) {
            const long long* t64 = (const long long*)tgt + (size_t)b * SEQLEN;
            cur = (int)t64[s];
            prv = (s == 0) ? START_TAG : (int)t64[s - 1];
        } else {
            const int* t32 = (const int*)tgt + b * SEQLEN;
            cur = t32[s];
            prv = (s == 0) ? START_TAG : t32[s - 1];
        }
        ts += tb[(size_t)s * NT2 + prv * NT + cur];
    }
    #pragma unroll
    for (int m = 16; m; m >>= 1) ts += __shfl_xor_sync(0xffffffffu, ts, m);
    if ((tid & 31) == 0) atomicAdd(&ts_sh, ts);

    // ---- forward recurrence with distance-2 register prefetch ----
    const int o0 = sub * NT + j;
    const int o1 = o0 +  8 * NT;
    const int o2 = o0 + 16 * NT;
    const int o3 = o0 + 24 * NT;
    const int o4 = o0 + 32 * NT;
    const int o5 = o0 + 40 * NT;

    float b0[6], b1[6], b2[6];
    {
        const float* p1 = tb + (size_t)1 * NT2;
        b1[0] = p1[o0]; b1[1] = p1[o1]; b1[2] = p1[o2];
        b1[3] = p1[o3]; b1[4] = p1[o4]; b1[5] = p1[o5];
        const float* p2 = tb + (size_t)2 * NT2;
        b2[0] = p2[o0]; b2[1] = p2[o1]; b2[2] = p2[o2];
        b2[3] = p2[o3]; b2[4] = p2[o4]; b2[5] = p2[o5];
    }
    float C = 0.0f;

#define STEP(T, CB, NB)                                                       \
    do {                                                                      \
        if ((T) + 2 < SEQLEN) {                                               \
            const float* pp = tb + (size_t)((T) + 2) * NT2;                   \
            NB[0] = pp[o0]; NB[1] = pp[o1]; NB[2] = pp[o2];                   \
            NB[3] = pp[o3]; NB[4] = pp[o4]; NB[5] = pp[o5];                   \
        }                                                                     \
        __syncthreads();                                                      \
        {                                                                     \
            const float* rin = shr[((T) + 1) & 1];                            \
            float m = rin[0];                                                 \
            C += m;                                                           \
            float e0 = __expf(rin[sub     ] - m + CB[0]);                     \
            float e1 = __expf(rin[sub +  8] - m + CB[1]);                     \
            float e2 = __expf(rin[sub + 16] - m + CB[2]);                     \
            float e3 = __expf(rin[sub + 24] - m + CB[3]);                     \
            float e4 = __expf(rin[sub + 32] - m + CB[4]);                     \
            float e5 = __expf(rin[sub + 40] - m + CB[5]);                     \
            float s = ((e0 + e1) + (e2 + e3)) + (e4 + e5);                    \
            s += __shfl_xor_sync(0xffffffffu, s, 1);                          \
            s += __shfl_xor_sync(0xffffffffu, s, 2);                          \
            s += __shfl_xor_sync(0xffffffffu, s, 4);                          \
            if (sub == 0) shr[(T) & 1][j] = __logf(s);                        \
        }                                                                     \
    } while (0)

    // 511 steps total: 170 x 3 unrolled + 1 tail. Buffer rotation:
    // step t consumes buf[t%3] and prefetches t+2 into buf[(t+2)%3].
    for (int it = 0; it < 170; ++it) {
        int t = 1 + it * 3;
        STEP(t,     b1, b0);
        STEP(t + 1, b2, b1);
        STEP(t + 2, b0, b2);
    }
    STEP(511, b1, b0);
#undef STEP

    __syncthreads();
    if (tid == 0) {
        float F = shr[1][END_TAG] + C;  // true forw[b, END]
        atomicAdd(out, (F - ts_sh) * (1.0f / (float)BSZ));
    }
}

extern "C" void kernel_launch(void* const* d_in, const int* in_sizes, int n_in,
                              void* d_out, int out_size) {
    const void* trans = d_in[0];
    const void* tgt   = d_in[1];
    // Defensive: identify tensors by size (transition is 75.5M elems, target 32K).
    if (n_in >= 2 && in_sizes[0] < in_sizes[1]) {
        trans = d_in[1];
        tgt   = d_in[0];
    }
    crf_prep<<<1, 32>>>((const int*)tgt, (float*)d_out);
    crf_main<<<BSZ, TPB>>>((const float*)trans, tgt, (float*)d_out);
}

// round 7
// speedup vs baseline: 1.5998x; 1.5998x over previous
#include <cuda_runtime.h>
#include <cuda_bf16.h>
#include <cstdint>
#include <cstddef>

#define BSZ       64
#define SEQLEN    512
#define NT        48
#define NT2       (NT * NT)        // 2304 floats / step tile
#define START_TAG 46
#define END_TAG   47
#define TPB       384              // 48 columns x 8 lanes
#define PD        4                // smem pipeline stages
#define ROWP      52               // padded row stride (floats) -> conflict-free LDS
#define TILE_F    (NT * ROWP)      // 2496 floats
#define TILE_B    (TILE_F * 4)     // 9984 bytes
#define NF4       (NT2 / 4)        // 576 float4 per tile

// Runtime-detected target dtype flag (1 = int64, 0 = int32).
__device__ int g_is64;

__global__ void crf_prep(const int* __restrict__ tgt32, float* __restrict__ out) {
    int lane = threadIdx.x;
    int v = tgt32[2 * lane + 1];
    int all0 = __all_sync(0xffffffffu, v == 0);
    if (lane == 0) {
        g_is64 = all0;
        out[0] = 0.0f;
    }
}

__device__ __forceinline__ void cpa16(uint32_t dst, const void* src) {
    asm volatile("cp.async.cg.shared.global [%0], [%1], 16;\n" :: "r"(dst), "l"(src));
}
__device__ __forceinline__ void cpa_commit() {
    asm volatile("cp.async.commit_group;\n" ::: "memory");
}
__device__ __forceinline__ void cpa_wait2() {
    asm volatile("cp.async.wait_group %0;\n" :: "n"(PD - 2) : "memory");
}

// One CTA per batch. 48 columns (j) x 8 reduction lanes (sub).
// Transition tiles stream through a PD-stage padded smem ring via cp.async:
//   - gmem side: 16B fully-coalesced copies (1 L1 line per 8 lanes)
//   - smem side: row stride 52 floats => LDS banks (20*sub + j) % 32, all
//     distinct within a warp => conflict-free scattered reads.
// LSE stability: running scalar offset m = r[0] per step, C accumulates m.
__global__ __launch_bounds__(TPB, 1) void crf_main(
    const float* __restrict__ tr,
    const void*  __restrict__ tgt,
    float*       __restrict__ out)
{
    __shared__ __align__(16) float tile[PD][TILE_F];
    __shared__ float shr[2][NT];
    __shared__ float ts_sh;

    const int tid = threadIdx.x;
    const int b   = blockIdx.x;
    const int j   = tid >> 3;   // column 0..47
    const int sub = tid & 7;    // reduction lane 0..7

    const float* __restrict__ tb = tr + (size_t)b * SEQLEN * NT2;

    if (tid == 0) ts_sh = 0.0f;
    // r_1 = transition[b, 0, START, :]  (t=0 tile is never staged)
    if (tid < NT) shr[0][tid] = tb[START_TAG * NT + tid];

    // ---- cp.async destination/source offsets (constant per thread) ----
    const uint32_t tbase = (uint32_t)__cvta_generic_to_shared(&tile[0][0]);
    const int f1 = tid;           // float4 index, all threads
    const int f2 = tid + TPB;     // second float4, threads < 192 only
    const uint32_t d1 = (uint32_t)((f1 / 12) * (ROWP * 4) + (f1 % 12) * 16);
    const uint32_t d2 = (uint32_t)((f2 / 12) * (ROWP * 4) + (f2 % 12) * 16);

    // ---- prologue: stage tiles for t = 1 .. PD-1 ----
    #pragma unroll
    for (int t = 1; t < PD; ++t) {
        uint32_t sb = tbase + (uint32_t)t * TILE_B;
        const char* s = (const char*)(tb + (size_t)t * NT2);
        cpa16(sb + d1, s + (size_t)f1 * 16);
        if (tid < NF4 - TPB) cpa16(sb + d2, s + (size_t)f2 * 16);
        cpa_commit();
    }

    // ---- target path score (one-off; overlaps with prologue loads) ----
    const int is64 = g_is64;
    float ts = 0.0f;
    for (int s = tid; s < SEQLEN; s += TPB) {
        int cur, prv;
        if (is64) {
            const long long* t64 = (const long long*)tgt + (size_t)b * SEQLEN;
            cur = (int)t64[s];
            prv = (s == 0) ? START_TAG : (int)t64[s - 1];
        } else {
            const int* t32 = (const int*)tgt + b * SEQLEN;
            cur = t32[s];
            prv = (s == 0) ? START_TAG : t32[s - 1];
        }
        ts += tb[(size_t)s * NT2 + prv * NT + cur];
    }
    #pragma unroll
    for (int m = 16; m; m >>= 1) ts += __shfl_xor_sync(0xffffffffu, ts, m);
    if ((tid & 31) == 0) atomicAdd(&ts_sh, ts);

    // ---- per-thread smem read offsets (conflict-free, see header) ----
    const int r0o = sub *  ROWP + j;
    const int r1o = r0o +  8 * ROWP;
    const int r2o = r0o + 16 * ROWP;
    const int r3o = r0o + 24 * ROWP;
    const int r4o = r0o + 32 * ROWP;
    const int r5o = r0o + 40 * ROWP;

    float C = 0.0f;

    // ---- forward recurrence t = 1 .. 511 ----
    for (int t = 1; t < SEQLEN; ++t) {
        // Retire the copy for this step's stage (oldest of <=3 in flight).
        cpa_wait2();
        __syncthreads();   // copies visible to all; stage (t-1)&3 reads done

        // Refill the just-freed stage with tile t+3.
        if (t + PD - 1 < SEQLEN) {
            uint32_t sb = tbase + (uint32_t)((t + PD - 1) & (PD - 1)) * TILE_B;
            const char* s = (const char*)(tb + (size_t)(t + PD - 1) * NT2);
            cpa16(sb + d1, s + (size_t)f1 * 16);
            if (tid < NF4 - TPB) cpa16(sb + d2, s + (size_t)f2 * 16);
        }
        cpa_commit();      // all threads commit every step (possibly empty)

        const float* __restrict__ tl  = tile[t & (PD - 1)];
        const float* __restrict__ rin = shr[(t + 1) & 1];
        const float  m = rin[0];
        C += m;
        float e0 = __expf(rin[sub     ] - m + tl[r0o]);
        float e1 = __expf(rin[sub +  8] - m + tl[r1o]);
        float e2 = __expf(rin[sub + 16] - m + tl[r2o]);
        float e3 = __expf(rin[sub + 24] - m + tl[r3o]);
        float e4 = __expf(rin[sub + 32] - m + tl[r4o]);
        float e5 = __expf(rin[sub + 40] - m + tl[r5o]);
        float s = ((e0 + e1) + (e2 + e3)) + (e4 + e5);
        s += __shfl_xor_sync(0xffffffffu, s, 1);
        s += __shfl_xor_sync(0xffffffffu, s, 2);
        s += __shfl_xor_sync(0xffffffffu, s, 4);
        if (sub == 0) shr[t & 1][j] = __logf(s);
    }

    __syncthreads();
    if (tid == 0) {
        float F = shr[(SEQLEN - 1) & 1][END_TAG] + C;  // forw[b, END]
        atomicAdd(out, (F - ts_sh) * (1.0f / (float)BSZ));
    }
}

extern "C" void kernel_launch(void* const* d_in, const int* in_sizes, int n_in,
                              void* d_out, int out_size) {
    const void* trans = d_in[0];
    const void* tgt   = d_in[1];
    // Defensive: identify tensors by size (transition is 75.5M elems).
    if (n_in >= 2 && in_sizes[0] < in_sizes[1]) {
        trans = d_in[1];
        tgt   = d_in[0];
    }
    crf_prep<<<1, 32>>>((const int*)tgt, (float*)d_out);
    crf_main<<<BSZ, TPB>>>((const float*)trans, tgt, (float*)d_out);
}

// round 8
// speedup vs baseline: 2.8125x; 1.7581x over previous
#include <cuda_runtime.h>
#include <cuda_bf16.h>
#include <cstdint>
#include <cstddef>

#define BSZ       64
#define SEQLEN    512
#define HALF      256              // forward covers tiles 1..255, backward 256..511
#define NSTEP     255              // sequential LSE steps per direction
#define NT        48
#define NT2       (NT * NT)        // 2304 floats / step tile
#define START_TAG 46
#define END_TAG   47
#define TPB       384              // 48 x 8
#define PD        4                // smem pipeline stages
#define ROWPF     52               // fwd pad: banks (20*sub+j)%32 distinct
#define ROWPB     40               // bwd pad: banks (8*i+sub)%32 distinct
#define TILE_B    (NT * ROWPF * 4) // stage stride in bytes (fwd size >= bwd size)
#define NF4       (NT2 / 4)        // 576 float4 per tile

// Cross-kernel scratch (no allocations allowed).
__device__ float g_fw[BSZ][NT + 1];   // [0..47]=forw_255, [48]=C offset
__device__ float g_bw[BSZ][NT + 1];   // [0..47]=beta_255, [48]=C offset
__device__ float g_ts[BSZ];           // target path score
__device__ int   g_is64;

__global__ void crf_prep(const int* __restrict__ tgt32, float* __restrict__ out) {
    int lane = threadIdx.x;
    int v = tgt32[2 * lane + 1];
    int all0 = __all_sync(0xffffffffu, v == 0);
    if (lane == 0) {
        g_is64 = all0;
        out[0] = 0.0f;
    }
}

__device__ __forceinline__ void cpa16(uint32_t dst, const void* src) {
    asm volatile("cp.async.cg.shared.global [%0], [%1], 16;\n" :: "r"(dst), "l"(src));
}
__device__ __forceinline__ void cpa_commit() {
    asm volatile("cp.async.commit_group;\n" ::: "memory");
}
__device__ __forceinline__ void cpa_wait2() {
    asm volatile("cp.async.wait_group %0;\n" :: "n"(PD - 2) : "memory");
}

// 128 CTAs: blockIdx.x = 2*b + dir. dir=0: forward recurrence over tiles
// 1..255 (also computes the target path score). dir=1: backward (beta)
// recurrence over tiles 511..256. Both are 48-wide LSE vector recurrences
// with a running scalar offset C (m = r[0] per step) for stability.
// Tiles stream through a PD-stage padded smem ring via coalesced 16B
// cp.async; padded row strides make the scattered LDS conflict-free.
__global__ __launch_bounds__(TPB, 1) void crf_main(
    const float* __restrict__ tr,
    const void*  __restrict__ tgt)
{
    __shared__ __align__(16) float tile[PD][NT * ROWPF];
    __shared__ float shr[2][NT];
    __shared__ float ts_sh;

    const int tid = threadIdx.x;
    const int b   = blockIdx.x >> 1;
    const int dir = blockIdx.x & 1;
    const int grp = tid >> 3;   // fwd: column j | bwd: row i
    const int sub = tid & 7;    // reduction lane

    const float* __restrict__ tb = tr + (size_t)b * SEQLEN * NT2;

    const uint32_t tbase = (uint32_t)__cvta_generic_to_shared(&tile[0][0]);
    const int f1 = tid;
    const int f2 = tid + TPB;
    const int rowp = dir ? ROWPB : ROWPF;
    const uint32_t d1 = (uint32_t)((f1 / 12) * (rowp * 4) + (f1 % 12) * 16);
    const uint32_t d2 = (uint32_t)((f2 / 12) * (rowp * 4) + (f2 % 12) * 16);

    // Step k consumes gmem tile T(k); fwd: T=k, bwd: T=511-k.
    #define TILE_T(k) (dir ? (SEQLEN - 1 - (k)) : (k))

    // ---- init r_0 in shr[0] ----
    if (tid == 0) ts_sh = 0.0f;
    if (tid < NT) {
        shr[0][tid] = dir
            ? tb[(size_t)(SEQLEN - 1) * NT2 + tid * NT + END_TAG]  // beta_510
            : tb[START_TAG * NT + tid];                             // forw_1
    }

    // ---- prologue: stage tiles for k = 1 .. PD-1 ----
    #pragma unroll
    for (int k = 1; k < PD; ++k) {
        uint32_t sb = tbase + (uint32_t)k * TILE_B;
        const char* s = (const char*)(tb + (size_t)TILE_T(k) * NT2);
        cpa16(sb + d1, s + (size_t)f1 * 16);
        if (tid < NF4 - TPB) cpa16(sb + d2, s + (size_t)f2 * 16);
        cpa_commit();
    }

    // ---- target path score (fwd CTA only; overlaps prologue latency) ----
    if (dir == 0) {
        const int is64 = g_is64;
        float ts = 0.0f;
        for (int s = tid; s < SEQLEN; s += TPB) {
            int cur, prv;
            if (is64) {
                const long long* t64 = (const long long*)tgt + (size_t)b * SEQLEN;
                cur = (int)t64[s];
                prv = (s == 0) ? START_TAG : (int)t64[s - 1];
            } else {
                const int* t32 = (const int*)tgt + b * SEQLEN;
                cur = t32[s];
                prv = (s == 0) ? START_TAG : t32[s - 1];
            }
            ts += tb[(size_t)s * NT2 + prv * NT + cur];
        }
        #pragma unroll
        for (int m = 16; m; m >>= 1) ts += __shfl_xor_sync(0xffffffffu, ts, m);
        if ((tid & 31) == 0) atomicAdd(&ts_sh, ts);
    }

    // ---- per-thread smem read offsets (conflict-free) ----
    // fwd: tile[sub*52 + j + 8k*52]   banks (20*sub+j)%32 distinct in warp
    // bwd: tile[i*40 + sub + 8k]      banks (8*i+sub)%32  distinct in warp
    const int step8 = dir ? 8 : (8 * ROWPF);
    const int q0 = dir ? (grp * ROWPB + sub) : (sub * ROWPF + grp);
    const int q1 = q0 + step8;
    const int q2 = q0 + 2 * step8;
    const int q3 = q0 + 3 * step8;
    const int q4 = q0 + 4 * step8;
    const int q5 = q0 + 5 * step8;

    float C = 0.0f;

    // ---- recurrence: k = 1 .. 255 ----
    for (int k = 1; k <= NSTEP; ++k) {
        cpa_wait2();
        __syncthreads();

        if (k + PD - 1 <= NSTEP) {
            uint32_t sb = tbase + (uint32_t)((k + PD - 1) & (PD - 1)) * TILE_B;
            const char* s = (const char*)(tb + (size_t)TILE_T(k + PD - 1) * NT2);
            cpa16(sb + d1, s + (size_t)f1 * 16);
            if (tid < NF4 - TPB) cpa16(sb + d2, s + (size_t)f2 * 16);
        }
        cpa_commit();

        const float* __restrict__ tl  = tile[k & (PD - 1)];
        const float* __restrict__ rin = shr[(k + 1) & 1];
        const float  m = rin[0];
        C += m;
        float e0 = __expf(rin[sub     ] - m + tl[q0]);
        float e1 = __expf(rin[sub +  8] - m + tl[q1]);
        float e2 = __expf(rin[sub + 16] - m + tl[q2]);
        float e3 = __expf(rin[sub + 24] - m + tl[q3]);
        float e4 = __expf(rin[sub + 32] - m + tl[q4]);
        float e5 = __expf(rin[sub + 40] - m + tl[q5]);
        float s = ((e0 + e1) + (e2 + e3)) + (e4 + e5);
        s += __shfl_xor_sync(0xffffffffu, s, 1);
        s += __shfl_xor_sync(0xffffffffu, s, 2);
        s += __shfl_xor_sync(0xffffffffu, s, 4);
        if (sub == 0) shr[k & 1][grp] = __logf(s);
    }

    __syncthreads();
    float* dst = dir ? g_bw[b] : g_fw[b];
    if (tid < NT) dst[tid] = shr[NSTEP & 1][tid];
    if (tid == 0) {
        dst[NT] = C;
        if (dir == 0) g_ts[b] = ts_sh;
    }
    #undef TILE_T
}

// Combine: forw_511[END] = LSE_i(forw_255[i] + beta_255[i]) + C_f + C_b.
__global__ void crf_combine(float* __restrict__ out) {
    const int b = blockIdx.x;
    const int i = threadIdx.x;   // 64 threads, 48 active
    __shared__ float sv[NT];
    if (i < NT) sv[i] = g_fw[b][i] + g_bw[b][i];
    __syncthreads();
    if (i == 0) {
        float m = sv[0];
        #pragma unroll
        for (int k = 1; k < NT; ++k) m = fmaxf(m, sv[k]);
        float s = 0.0f;
        #pragma unroll
        for (int k = 0; k < NT; ++k) s += __expf(sv[k] - m);
        float F = __logf(s) + m + g_fw[b][NT] + g_bw[b][NT];
        atomicAdd(out, (F - g_ts[b]) * (1.0f / (float)BSZ));
    }
}

extern "C" void kernel_launch(void* const* d_in, const int* in_sizes, int n_in,
                              void* d_out, int out_size) {
    const void* trans = d_in[0];
    const void* tgt   = d_in[1];
    // Defensive: identify tensors by size (transition is 75.5M elems).
    if (n_in >= 2 && in_sizes[0] < in_sizes[1]) {
        trans = d_in[1];
        tgt   = d_in[0];
    }
    crf_prep<<<1, 32>>>((const int*)tgt, (float*)d_out);
    crf_main<<<2 * BSZ, TPB>>>((const float*)trans, tgt);
    crf_combine<<<BSZ, 64>>>((float*)d_out);
}